// round 1
// baseline (speedup 1.0000x reference)
#include <cuda_runtime.h>
#include <stdint.h>

// Problem constants
#define N_V   16384          // vertices (rows of H)
#define N_E   8192           // hyperedges (cols of H)
#define CIN   128
#define COUT  64
#define LOG_M 13             // log2(N_E)

// Extraction config
#define EBLOCKS  2048
#define ETHREADS 256
#define CAPB     512                       // COO slots per block (mean ~328, 10 sigma safe)
#define NTOT     (EBLOCKS*ETHREADS)        // 524288 threads
#define EITER    64                        // (N_V*N_E/4)/NTOT exactly

// ---------------- scratch (device globals; no allocation) ----------------
__device__ int            g_deg_v[N_V];
__device__ int            g_deg_e[N_E];
__device__ int            g_cur_v[N_V];
__device__ int            g_cur_e[N_E];
__device__ int            g_off_v[N_V + 1];
__device__ int            g_off_e[N_E + 1];
__device__ int            g_blk_cnt[EBLOCKS];
__device__ unsigned int   g_coo[EBLOCKS * CAPB];     // packed (i<<13)|j
__device__ unsigned short g_adj_v[EBLOCKS * CAPB];   // CSR by vertex: edge ids
__device__ unsigned short g_adj_e[EBLOCKS * CAPB];   // CSC by edge: vertex ids
__device__ float          g_dv[N_V];
__device__ float          g_de[N_E];
__device__ float          g_Z[N_V * COUT];           // dv * (X W^T + b)
__device__ float          g_Y2[N_E * COUT];          // de * (H^T @ Z)

// ---------------- kernels ----------------

__global__ void k_init() {
    int t = blockIdx.x * blockDim.x + threadIdx.x;
    if (t < N_V) { g_deg_v[t] = 0; g_cur_v[t] = 0; }
    if (t < N_E) { g_deg_e[t] = 0; g_cur_e[t] = 0; }
}

// One streaming pass over H (536 MB): degree counts + per-block COO regions.
// H entries are exactly 0.0f or 1.0f -> integer nonzero test is valid.
__global__ void k_extract(const float* __restrict__ H) {
    __shared__ int s_cnt;
    if (threadIdx.x == 0) s_cnt = 0;
    __syncthreads();

    const uint4* __restrict__ H4 = (const uint4*)H;
    int tid = blockIdx.x * ETHREADS + threadIdx.x;
    unsigned cooBase = blockIdx.x * CAPB;

#pragma unroll 4
    for (int it = 0; it < EITER; it++) {
        int v = tid + it * NTOT;           // max 33.5M, fits int
        uint4 h = H4[v];
        if ((h.x | h.y | h.z | h.w) == 0u) continue;   // ~98% of vectors
        int e = v * 4;
#pragma unroll
        for (int c = 0; c < 4; c++) {
            unsigned hv = (c == 0) ? h.x : (c == 1) ? h.y : (c == 2) ? h.z : h.w;
            if (hv) {
                int ee = e + c;
                int i = ee >> LOG_M;
                int j = ee & (N_E - 1);
                atomicAdd(&g_deg_v[i], 1);
                atomicAdd(&g_deg_e[j], 1);
                int p = atomicAdd(&s_cnt, 1);          // shared atomic: cheap
                if (p < CAPB)
                    g_coo[cooBase + p] = ((unsigned)i << LOG_M) | (unsigned)j;
            }
        }
    }
    __syncthreads();
    if (threadIdx.x == 0)
        g_blk_cnt[blockIdx.x] = (s_cnt < CAPB) ? s_cnt : CAPB;
}

// Single-block exclusive scan (n divisible by 1024)
__device__ void scan_block(const int* __restrict__ deg, int* __restrict__ off, int n) {
    __shared__ int part[1024];
    int tid = threadIdx.x;
    int per = n >> 10;
    int base = tid * per;
    int s = 0;
    for (int k = 0; k < per; k++) s += deg[base + k];
    part[tid] = s;
    __syncthreads();
    for (int d = 1; d < 1024; d <<= 1) {
        int v = (tid >= d) ? part[tid - d] : 0;
        __syncthreads();
        part[tid] += v;
        __syncthreads();
    }
    int pre = tid ? part[tid - 1] : 0;
    for (int k = 0; k < per; k++) { off[base + k] = pre; pre += deg[base + k]; }
    if (tid == 1023) off[n] = pre;
}

__global__ void k_scan() {
    if (blockIdx.x == 0) scan_block(g_deg_v, g_off_v, N_V);
    else                 scan_block(g_deg_e, g_off_e, N_E);
}

__global__ void k_scales() {
    int t = blockIdx.x * blockDim.x + threadIdx.x;
    if (t < N_V) {
        int d = g_deg_v[t];
        g_dv[t] = (d > 0) ? rsqrtf((float)d) : 0.0f;
    }
    if (t < N_E) {
        int d = g_deg_e[t];
        g_de[t] = (d > 0) ? (1.0f / (float)d) : 0.0f;
    }
}

// Bucket COO into vertex-CSR and edge-CSC adjacency lists
__global__ void k_bucket() {
    int idx = blockIdx.x * blockDim.x + threadIdx.x;   // over EBLOCKS*CAPB slots
    int blk = idx >> 9;                                // CAPB = 512
    int loc = idx & (CAPB - 1);
    if (loc >= g_blk_cnt[blk]) return;
    unsigned p = g_coo[idx];
    int i = p >> LOG_M;
    int j = p & (N_E - 1);
    int pv = atomicAdd(&g_cur_v[i], 1);
    g_adj_v[g_off_v[i] + pv] = (unsigned short)j;
    int pe = atomicAdd(&g_cur_e[j], 1);
    g_adj_e[g_off_e[j] + pe] = (unsigned short)i;
}

// Z[i][c] = dv[i] * (sum_k X[i][k]*W[c][k] + b[c])
// Block: 32 rows x 64 cols, 128 threads, 4x4 register tile.
__global__ void k_gemm(const float* __restrict__ X,
                       const float* __restrict__ W,
                       const float* __restrict__ b) {
    __shared__ float Xs[32 * 128];   // 16 KB
    __shared__ float Ws[128 * 64];   // 32 KB  [k][c]  (total 48 KB exactly)
    int tid = threadIdx.x;           // 128 threads
    int row0 = blockIdx.x * 32;

    // Load X tile (coalesced, float4)
    const float4* __restrict__ Xg = (const float4*)(X + row0 * CIN);
    float4* Xs4 = (float4*)Xs;
#pragma unroll
    for (int t = 0; t < 8; t++) Xs4[tid + t * 128] = Xg[tid + t * 128];

    // Load W transposed into Ws[k][c]; gmem reads scattered (L1/L2 served),
    // smem stores conflict-free.
#pragma unroll
    for (int t = 0; t < 64; t++) {
        int idx = tid + t * 128;     // idx = k*64 + c
        int k = idx >> 6, c = idx & 63;
        Ws[idx] = W[c * CIN + k];
    }
    __syncthreads();

    int cx = (tid & 15) * 4;
    int ry = (tid >> 4) * 4;
    float acc[4][4] = {};

#pragma unroll
    for (int k = 0; k < 128; k += 4) {
        float4 wv[4], xv[4];
#pragma unroll
        for (int u = 0; u < 4; u++) wv[u] = *(const float4*)&Ws[(k + u) * 64 + cx];
#pragma unroll
        for (int r = 0; r < 4; r++) xv[r] = *(const float4*)&Xs[(ry + r) * 128 + k];
#pragma unroll
        for (int r = 0; r < 4; r++) {
            acc[r][0] += xv[r].x * wv[0].x + xv[r].y * wv[1].x + xv[r].z * wv[2].x + xv[r].w * wv[3].x;
            acc[r][1] += xv[r].x * wv[0].y + xv[r].y * wv[1].y + xv[r].z * wv[2].y + xv[r].w * wv[3].y;
            acc[r][2] += xv[r].x * wv[0].z + xv[r].y * wv[1].z + xv[r].z * wv[2].z + xv[r].w * wv[3].z;
            acc[r][3] += xv[r].x * wv[0].w + xv[r].y * wv[1].w + xv[r].z * wv[2].w + xv[r].w * wv[3].w;
        }
    }

    float b0 = b[cx], b1 = b[cx + 1], b2 = b[cx + 2], b3 = b[cx + 3];
#pragma unroll
    for (int r = 0; r < 4; r++) {
        int i = row0 + ry + r;
        float s = g_dv[i];
        float4 o;
        o.x = s * (acc[r][0] + b0);
        o.y = s * (acc[r][1] + b1);
        o.z = s * (acc[r][2] + b2);
        o.w = s * (acc[r][3] + b3);
        *(float4*)&g_Z[i * COUT + cx] = o;
    }
}

// Y2[j] = de[j] * sum_{i in edge j} Z[i]     (warp per edge, Z in L2)
__global__ void k_edge() {
    int w = (blockIdx.x * blockDim.x + threadIdx.x) >> 5;
    int lane = threadIdx.x & 31;
    if (w >= N_E) return;
    int t = g_off_e[w], end = g_off_e[w + 1];
    float a0 = 0.f, a1 = 0.f, b0 = 0.f, b1 = 0.f;
    for (; t + 2 <= end; t += 2) {
        int i0 = g_adj_e[t], i1 = g_adj_e[t + 1];
        const float* z0 = g_Z + i0 * COUT;
        const float* z1 = g_Z + i1 * COUT;
        a0 += z0[lane]; a1 += z0[lane + 32];
        b0 += z1[lane]; b1 += z1[lane + 32];
    }
    if (t < end) {
        int i0 = g_adj_e[t];
        const float* z0 = g_Z + i0 * COUT;
        a0 += z0[lane]; a1 += z0[lane + 32];
    }
    float de = g_de[w];
    g_Y2[w * COUT + lane]      = (a0 + b0) * de;
    g_Y2[w * COUT + lane + 32] = (a1 + b1) * de;
}

// out[i] = relu(dv[i] * sum_{j in vertex i} Y2[j])   (warp per vertex, Y2 in L2)
__global__ void k_vertex(float* __restrict__ out) {
    int w = (blockIdx.x * blockDim.x + threadIdx.x) >> 5;
    int lane = threadIdx.x & 31;
    if (w >= N_V) return;
    int t = g_off_v[w], end = g_off_v[w + 1];
    float a0 = 0.f, a1 = 0.f, b0 = 0.f, b1 = 0.f;
    for (; t + 2 <= end; t += 2) {
        int j0 = g_adj_v[t], j1 = g_adj_v[t + 1];
        const float* y0 = g_Y2 + j0 * COUT;
        const float* y1 = g_Y2 + j1 * COUT;
        a0 += y0[lane]; a1 += y0[lane + 32];
        b0 += y1[lane]; b1 += y1[lane + 32];
    }
    if (t < end) {
        int j0 = g_adj_v[t];
        const float* y0 = g_Y2 + j0 * COUT;
        a0 += y0[lane]; a1 += y0[lane + 32];
    }
    float dv = g_dv[w];
    float o0 = dv * (a0 + b0);
    float o1 = dv * (a1 + b1);
    out[w * COUT + lane]      = o0 > 0.f ? o0 : 0.f;
    out[w * COUT + lane + 32] = o1 > 0.f ? o1 : 0.f;
}

// ---------------- launch ----------------
extern "C" void kernel_launch(void* const* d_in, const int* in_sizes, int n_in,
                              void* d_out, int out_size) {
    const float* X = (const float*)d_in[0];   // (N_V, 128)
    const float* H = (const float*)d_in[1];   // (N_V, N_E)
    const float* W = (const float*)d_in[2];   // (64, 128)
    const float* b = (const float*)d_in[3];   // (64,)
    float* out = (float*)d_out;               // (N_V, 64)

    k_init   <<<64, 256>>>();
    k_extract<<<EBLOCKS, ETHREADS>>>(H);
    k_scan   <<<2, 1024>>>();
    k_scales <<<64, 256>>>();
    k_bucket <<<(EBLOCKS * CAPB) / 256, 256>>>();
    k_gemm   <<<N_V / 32, 128>>>(X, W, b);
    k_edge   <<<(N_E * 32) / 256, 256>>>();
    k_vertex <<<(N_V * 32) / 256, 256>>>(out);
}